// round 1
// baseline (speedup 1.0000x reference)
#include <cuda_runtime.h>
#include <cstddef>

#define D_MODEL 1024
#define SEQ     2048
#define BATCH   4
#define HEADS   16
#define HDIM    64
#define MROWS   (BATCH * SEQ)   /* 8192 */

// Scratch (alloc-free rule: __device__ globals)
__device__ float g_q[MROWS * D_MODEL];
__device__ float g_k[MROWS * D_MODEL];
__device__ float g_v[MROWS * D_MODEL];
__device__ float g_o[MROWS * D_MODEL];

// ---------------------------------------------------------------------------
// SGEMM: C[M,N] = A[M,K] @ B[K,N] + bias[N]
// 128x128 tile, BK=8, 256 threads, 8x8 per-thread microtile.
// M % 128 == 0, N % 128 == 0, K % 8 == 0 (true for all our shapes).
// ---------------------------------------------------------------------------
__global__ __launch_bounds__(256) void sgemm_bias(
    const float* __restrict__ A, const float* __restrict__ B,
    const float* __restrict__ bias, float* __restrict__ C,
    int M, int N, int K)
{
    __shared__ float As[8][128];   // transposed A tile: [k][m]
    __shared__ float Bs[8][128];   // [k][n]

    const int tid = threadIdx.x;
    const int tx  = tid & 15;      // 0..15  (N dir)
    const int ty  = tid >> 4;      // 0..15  (M dir)
    const int row0 = blockIdx.y * 128;
    const int col0 = blockIdx.x * 128;

    float acc[8][8];
#pragma unroll
    for (int i = 0; i < 8; i++)
#pragma unroll
        for (int j = 0; j < 8; j++) acc[i][j] = 0.f;

    const int aRow = tid >> 1;          // 0..127
    const int aCol = (tid & 1) * 4;     // 0 or 4
    const int bRow = tid >> 5;          // 0..7
    const int bCol = (tid & 31) * 4;    // 0..124

    const float* Aptr = A + (size_t)(row0 + aRow) * K + aCol;
    const float* Bptr = B + (size_t)bRow * N + col0 + bCol;

    for (int k0 = 0; k0 < K; k0 += 8) {
        float4 av = *(const float4*)(Aptr + k0);
        As[aCol + 0][aRow] = av.x;
        As[aCol + 1][aRow] = av.y;
        As[aCol + 2][aRow] = av.z;
        As[aCol + 3][aRow] = av.w;
        float4 bv = *(const float4*)(Bptr + (size_t)k0 * N);
        *(float4*)&Bs[bRow][bCol] = bv;
        __syncthreads();

#pragma unroll
        for (int kk = 0; kk < 8; kk++) {
            float4 a0 = *(const float4*)&As[kk][ty * 8];
            float4 a1 = *(const float4*)&As[kk][ty * 8 + 4];
            float4 b0 = *(const float4*)&Bs[kk][tx * 8];
            float4 b1 = *(const float4*)&Bs[kk][tx * 8 + 4];
            float a[8] = {a0.x, a0.y, a0.z, a0.w, a1.x, a1.y, a1.z, a1.w};
            float b[8] = {b0.x, b0.y, b0.z, b0.w, b1.x, b1.y, b1.z, b1.w};
#pragma unroll
            for (int i = 0; i < 8; i++)
#pragma unroll
                for (int j = 0; j < 8; j++)
                    acc[i][j] = fmaf(a[i], b[j], acc[i][j]);
        }
        __syncthreads();
    }

#pragma unroll
    for (int i = 0; i < 8; i++) {
        const int r = row0 + ty * 8 + i;
#pragma unroll
        for (int j = 0; j < 8; j += 4) {
            const int c = col0 + tx * 8 + j;
            float4 ov;
            ov.x = acc[i][j + 0] + bias[c + 0];
            ov.y = acc[i][j + 1] + bias[c + 1];
            ov.z = acc[i][j + 2] + bias[c + 2];
            ov.w = acc[i][j + 3] + bias[c + 3];
            *(float4*)&C[(size_t)r * N + c] = ov;
        }
    }
}

// ---------------------------------------------------------------------------
// Causal flash attention, fp32.
// Grid: (SEQ/64, BATCH*HEADS), 256 threads.
// Q tile 64 rows; K/V tiles of 64 processed up to (and including) diagonal.
// Thread (ty,tx) owns rows r=ty*4..+3, cols c=tx*4..+3 of the 64x64 tiles.
// Smem: exactly 48KB static (Qs + K/P alias + Vs).
// ---------------------------------------------------------------------------
__global__ __launch_bounds__(256) void attn_causal(
    const float* __restrict__ q, const float* __restrict__ k,
    const float* __restrict__ v, float* __restrict__ o)
{
    __shared__ float Qs[64][64];   // [d][r]  (transposed)
    __shared__ float KPs[64][64];  // K phase: [d][c]; P phase: [c][r]
    __shared__ float Vs[64][64];   // [c][dd]

    const int tid = threadIdx.x;
    const int tx  = tid & 15;
    const int ty  = tid >> 4;
    const int qt  = blockIdx.x;
    const int bh  = blockIdx.y;
    const int b   = bh >> 4;
    const int h   = bh & 15;
    const int qbase = qt * 64;

    const float* qp = q + ((size_t)b * SEQ + qbase) * D_MODEL + h * HDIM;

    // Load Q tile transposed, pre-scaled by 1/sqrt(hd)
    for (int idx = tid; idx < 64 * 64; idx += 256) {
        const int r = idx >> 6, d = idx & 63;
        Qs[d][r] = qp[(size_t)r * D_MODEL + d] * 0.125f;
    }

    float m_i[4], l_i[4], acc[4][4];
#pragma unroll
    for (int i = 0; i < 4; i++) {
        m_i[i] = -1e30f;
        l_i[i] = 0.f;
#pragma unroll
        for (int j = 0; j < 4; j++) acc[i][j] = 0.f;
    }
    __syncthreads();

    const int nkt = qt + 1;
    for (int kt = 0; kt < nkt; kt++) {
        const int kbase = kt * 64;
        const float* kp = k + ((size_t)b * SEQ + kbase) * D_MODEL + h * HDIM;
        const float* vp = v + ((size_t)b * SEQ + kbase) * D_MODEL + h * HDIM;
        for (int idx = tid; idx < 64 * 64; idx += 256) {
            const int c = idx >> 6, d = idx & 63;
            KPs[d][c] = kp[(size_t)c * D_MODEL + d];
            Vs[c][d]  = vp[(size_t)c * D_MODEL + d];
        }
        __syncthreads();

        // S = Q @ K^T  (per-thread 4x4)
        float s[4][4];
#pragma unroll
        for (int i = 0; i < 4; i++)
#pragma unroll
            for (int j = 0; j < 4; j++) s[i][j] = 0.f;

#pragma unroll 8
        for (int d = 0; d < 64; d++) {
            float4 av = *(const float4*)&Qs[d][ty * 4];
            float4 bv = *(const float4*)&KPs[d][tx * 4];
            float a[4] = {av.x, av.y, av.z, av.w};
            float bb[4] = {bv.x, bv.y, bv.z, bv.w};
#pragma unroll
            for (int i = 0; i < 4; i++)
#pragma unroll
                for (int j = 0; j < 4; j++)
                    s[i][j] = fmaf(a[i], bb[j], s[i][j]);
        }

        // Causal mask on diagonal tile (col > row masked)
        if (kt == qt) {
#pragma unroll
            for (int i = 0; i < 4; i++) {
                const int r = ty * 4 + i;
#pragma unroll
                for (int j = 0; j < 4; j++) {
                    const int c = tx * 4 + j;
                    if (c > r) s[i][j] = -1e30f;
                }
            }
        }

        // Online softmax per row (reduce across tx: lanes xor 1,2,4,8)
#pragma unroll
        for (int i = 0; i < 4; i++) {
            float mx = fmaxf(fmaxf(s[i][0], s[i][1]), fmaxf(s[i][2], s[i][3]));
#pragma unroll
            for (int off = 8; off >= 1; off >>= 1)
                mx = fmaxf(mx, __shfl_xor_sync(0xffffffffu, mx, off));
            const float mnew  = fmaxf(m_i[i], mx);
            const float scale = __expf(m_i[i] - mnew);
            float rs = 0.f;
#pragma unroll
            for (int j = 0; j < 4; j++) {
                s[i][j] = __expf(s[i][j] - mnew);
                rs += s[i][j];
            }
#pragma unroll
            for (int off = 8; off >= 1; off >>= 1)
                rs += __shfl_xor_sync(0xffffffffu, rs, off);
            l_i[i] = l_i[i] * scale + rs;
            m_i[i] = mnew;
#pragma unroll
            for (int j = 0; j < 4; j++) acc[i][j] *= scale;
        }

        __syncthreads();   // everyone done reading K from KPs
        // Write P transposed: KPs[c][r]
#pragma unroll
        for (int i = 0; i < 4; i++)
#pragma unroll
            for (int j = 0; j < 4; j++)
                KPs[tx * 4 + j][ty * 4 + i] = s[i][j];
        __syncthreads();

        // O += P @ V
#pragma unroll 8
        for (int c = 0; c < 64; c++) {
            float4 av = *(const float4*)&KPs[c][ty * 4];
            float4 bv = *(const float4*)&Vs[c][tx * 4];
            float a[4] = {av.x, av.y, av.z, av.w};
            float bb[4] = {bv.x, bv.y, bv.z, bv.w};
#pragma unroll
            for (int i = 0; i < 4; i++)
#pragma unroll
                for (int j = 0; j < 4; j++)
                    acc[i][j] = fmaf(a[i], bb[j], acc[i][j]);
        }
        __syncthreads();   // before next tile overwrites KPs/Vs
    }

    // Epilogue: normalize and store
    float* op = o + ((size_t)b * SEQ + qbase) * D_MODEL + h * HDIM;
#pragma unroll
    for (int i = 0; i < 4; i++) {
        const float inv = 1.f / l_i[i];
        const int r = ty * 4 + i;
#pragma unroll
        for (int j = 0; j < 4; j++)
            op[(size_t)r * D_MODEL + tx * 4 + j] = acc[i][j] * inv;
    }
}

// ---------------------------------------------------------------------------
extern "C" void kernel_launch(void* const* d_in, const int* in_sizes, int n_in,
                              void* d_out, int out_size)
{
    (void)in_sizes; (void)n_in; (void)out_size;
    const float* x  = (const float*)d_in[0];
    const float* Wq = (const float*)d_in[1];
    const float* bq = (const float*)d_in[2];
    const float* Wk = (const float*)d_in[3];
    const float* bk = (const float*)d_in[4];
    const float* Wv = (const float*)d_in[5];
    const float* bv = (const float*)d_in[6];
    const float* Wo = (const float*)d_in[7];
    const float* bo = (const float*)d_in[8];
    float* out = (float*)d_out;

    float *gq, *gk, *gv, *go;
    cudaGetSymbolAddress((void**)&gq, g_q);
    cudaGetSymbolAddress((void**)&gk, g_k);
    cudaGetSymbolAddress((void**)&gv, g_v);
    cudaGetSymbolAddress((void**)&go, g_o);

    dim3 gg(D_MODEL / 128, MROWS / 128);   // (8, 64)
    sgemm_bias<<<gg, 256>>>(x, Wq, bq, gq, MROWS, D_MODEL, D_MODEL);
    sgemm_bias<<<gg, 256>>>(x, Wk, bk, gk, MROWS, D_MODEL, D_MODEL);
    sgemm_bias<<<gg, 256>>>(x, Wv, bv, gv, MROWS, D_MODEL, D_MODEL);

    dim3 ga(SEQ / 64, BATCH * HEADS);       // (32, 64)
    attn_causal<<<ga, 256>>>(gq, gk, gv, go);

    sgemm_bias<<<gg, 256>>>(go, Wo, bo, out, MROWS, D_MODEL, D_MODEL);
}

// round 2
// speedup vs baseline: 1.1365x; 1.1365x over previous
#include <cuda_runtime.h>
#include <mma.h>
#include <cstddef>

using namespace nvcuda;

#define D_MODEL 1024
#define SEQ     2048
#define BATCH   4
#define HEADS   16
#define HDIM    64
#define MROWS   (BATCH * SEQ)   /* 8192 */

// Scratch (alloc-free rule: __device__ globals)
__device__ float g_q[MROWS * D_MODEL];
__device__ float g_k[MROWS * D_MODEL];
__device__ float g_v[MROWS * D_MODEL];
__device__ float g_o[MROWS * D_MODEL];

// ---------------------------------------------------------------------------
// TF32 tensor-core GEMM: C[M,N] = A[M,K] @ B[K,N] + bias[N]
// 128x128x32 block tile, 256 threads = 8 warps in 4x2 grid,
// warp tile 32x64 = 2x4 wmma m16n16k8 accumulators.
// Bias is pre-loaded into the accumulator fragments via a broadcast tile.
// ---------------------------------------------------------------------------
#define BM 128
#define BN 128
#define BK 32
#define LDA 40    // BK + 8 pad  (multiple of 4 for wmma, 16B-aligned rows)
#define LDB 136   // BN + 8 pad

__global__ __launch_bounds__(256) void gemm_tf32_bias(
    const float* __restrict__ A, const float* __restrict__ B,
    const float* __restrict__ bias, float* __restrict__ C,
    int M, int N, int K)
{
    __shared__ __align__(16) float As[BM][LDA];     // 20480 B
    __shared__ __align__(16) float Bs[BK][LDB];     // 17408 B
    __shared__ __align__(16) float BiasT[16][LDB];  //  8704 B  (16 identical rows)

    const int tid  = threadIdx.x;
    const int wid  = tid >> 5;
    const int wm   = wid >> 1;        // 0..3  (row of warp grid)
    const int wn   = wid & 1;         // 0..1  (col of warp grid)
    const int row0 = blockIdx.y * BM;
    const int col0 = blockIdx.x * BN;

    // Broadcast bias into 16 identical rows so it can seed the accumulators.
    for (int idx = tid; idx < 16 * BN; idx += 256) {
        const int r = idx >> 7, c = idx & 127;
        BiasT[r][c] = bias[col0 + c];
    }
    __syncthreads();

    wmma::fragment<wmma::accumulator, 16, 16, 8, float> acc[2][4];
#pragma unroll
    for (int i = 0; i < 2; i++)
#pragma unroll
        for (int j = 0; j < 4; j++)
            wmma::load_matrix_sync(acc[i][j], &BiasT[0][wn * 64 + j * 16],
                                   LDB, wmma::mem_row_major);
    __syncthreads();

    const int arow = tid >> 3;          // 0..31  (+i*32)
    const int acol = (tid & 7) * 4;     // 0..28
    const int brow = tid >> 6;          // 0..3   (+i*4 -> 0..31? use >>5)
    const int brow5 = tid >> 5;         // 0..7   (+i*8)
    const int bcol = (tid & 31) * 4;    // 0..124

    for (int k0 = 0; k0 < K; k0 += BK) {
        // A tile 128x32: 4 float4 per thread
#pragma unroll
        for (int i = 0; i < 4; i++) {
            const int r = arow + i * 32;
            float4 v = *(const float4*)&A[(size_t)(row0 + r) * K + k0 + acol];
            *(float4*)&As[r][acol] = v;
        }
        // B tile 32x128: 4 float4 per thread
#pragma unroll
        for (int i = 0; i < 4; i++) {
            const int r = brow5 + i * 8;
            float4 v = *(const float4*)&B[(size_t)(k0 + r) * N + col0 + bcol];
            *(float4*)&Bs[r][bcol] = v;
        }
        __syncthreads();

#pragma unroll
        for (int kk = 0; kk < BK; kk += 8) {
            wmma::fragment<wmma::matrix_a, 16, 16, 8, wmma::precision::tf32,
                           wmma::row_major> af[2];
            wmma::fragment<wmma::matrix_b, 16, 16, 8, wmma::precision::tf32,
                           wmma::row_major> bf[4];
#pragma unroll
            for (int i = 0; i < 2; i++) {
                wmma::load_matrix_sync(af[i], &As[wm * 32 + i * 16][kk], LDA);
#pragma unroll
                for (int t = 0; t < af[i].num_elements; t++)
                    af[i].x[t] = wmma::__float_to_tf32(af[i].x[t]);
            }
#pragma unroll
            for (int j = 0; j < 4; j++) {
                wmma::load_matrix_sync(bf[j], &Bs[kk][wn * 64 + j * 16], LDB);
#pragma unroll
                for (int t = 0; t < bf[j].num_elements; t++)
                    bf[j].x[t] = wmma::__float_to_tf32(bf[j].x[t]);
            }
#pragma unroll
            for (int i = 0; i < 2; i++)
#pragma unroll
                for (int j = 0; j < 4; j++)
                    wmma::mma_sync(acc[i][j], af[i], bf[j], acc[i][j]);
        }
        __syncthreads();
    }

    (void)brow;
#pragma unroll
    for (int i = 0; i < 2; i++)
#pragma unroll
        for (int j = 0; j < 4; j++) {
            float* cp = &C[(size_t)(row0 + wm * 32 + i * 16) * N +
                           col0 + wn * 64 + j * 16];
            wmma::store_matrix_sync(cp, acc[i][j], N, wmma::mem_row_major);
        }
}

// ---------------------------------------------------------------------------
// Causal flash attention, fp32 (unchanged from round 1).
// ---------------------------------------------------------------------------
__global__ __launch_bounds__(256) void attn_causal(
    const float* __restrict__ q, const float* __restrict__ k,
    const float* __restrict__ v, float* __restrict__ o)
{
    __shared__ float Qs[64][64];
    __shared__ float KPs[64][64];
    __shared__ float Vs[64][64];

    const int tid = threadIdx.x;
    const int tx  = tid & 15;
    const int ty  = tid >> 4;
    const int qt  = blockIdx.x;
    const int bh  = blockIdx.y;
    const int b   = bh >> 4;
    const int h   = bh & 15;
    const int qbase = qt * 64;

    const float* qp = q + ((size_t)b * SEQ + qbase) * D_MODEL + h * HDIM;

    for (int idx = tid; idx < 64 * 64; idx += 256) {
        const int r = idx >> 6, d = idx & 63;
        Qs[d][r] = qp[(size_t)r * D_MODEL + d] * 0.125f;
    }

    float m_i[4], l_i[4], acc[4][4];
#pragma unroll
    for (int i = 0; i < 4; i++) {
        m_i[i] = -1e30f;
        l_i[i] = 0.f;
#pragma unroll
        for (int j = 0; j < 4; j++) acc[i][j] = 0.f;
    }
    __syncthreads();

    const int nkt = qt + 1;
    for (int kt = 0; kt < nkt; kt++) {
        const int kbase = kt * 64;
        const float* kp = k + ((size_t)b * SEQ + kbase) * D_MODEL + h * HDIM;
        const float* vp = v + ((size_t)b * SEQ + kbase) * D_MODEL + h * HDIM;
        for (int idx = tid; idx < 64 * 64; idx += 256) {
            const int c = idx >> 6, d = idx & 63;
            KPs[d][c] = kp[(size_t)c * D_MODEL + d];
            Vs[c][d]  = vp[(size_t)c * D_MODEL + d];
        }
        __syncthreads();

        float s[4][4];
#pragma unroll
        for (int i = 0; i < 4; i++)
#pragma unroll
            for (int j = 0; j < 4; j++) s[i][j] = 0.f;

#pragma unroll 8
        for (int d = 0; d < 64; d++) {
            float4 av = *(const float4*)&Qs[d][ty * 4];
            float4 bv = *(const float4*)&KPs[d][tx * 4];
            float a[4] = {av.x, av.y, av.z, av.w};
            float bb[4] = {bv.x, bv.y, bv.z, bv.w};
#pragma unroll
            for (int i = 0; i < 4; i++)
#pragma unroll
                for (int j = 0; j < 4; j++)
                    s[i][j] = fmaf(a[i], bb[j], s[i][j]);
        }

        if (kt == qt) {
#pragma unroll
            for (int i = 0; i < 4; i++) {
                const int r = ty * 4 + i;
#pragma unroll
                for (int j = 0; j < 4; j++) {
                    const int c = tx * 4 + j;
                    if (c > r) s[i][j] = -1e30f;
                }
            }
        }

#pragma unroll
        for (int i = 0; i < 4; i++) {
            float mx = fmaxf(fmaxf(s[i][0], s[i][1]), fmaxf(s[i][2], s[i][3]));
#pragma unroll
            for (int off = 8; off >= 1; off >>= 1)
                mx = fmaxf(mx, __shfl_xor_sync(0xffffffffu, mx, off));
            const float mnew  = fmaxf(m_i[i], mx);
            const float scale = __expf(m_i[i] - mnew);
            float rs = 0.f;
#pragma unroll
            for (int j = 0; j < 4; j++) {
                s[i][j] = __expf(s[i][j] - mnew);
                rs += s[i][j];
            }
#pragma unroll
            for (int off = 8; off >= 1; off >>= 1)
                rs += __shfl_xor_sync(0xffffffffu, rs, off);
            l_i[i] = l_i[i] * scale + rs;
            m_i[i] = mnew;
#pragma unroll
            for (int j = 0; j < 4; j++) acc[i][j] *= scale;
        }

        __syncthreads();
#pragma unroll
        for (int i = 0; i < 4; i++)
#pragma unroll
            for (int j = 0; j < 4; j++)
                KPs[tx * 4 + j][ty * 4 + i] = s[i][j];
        __syncthreads();

#pragma unroll 8
        for (int c = 0; c < 64; c++) {
            float4 av = *(const float4*)&KPs[c][ty * 4];
            float4 bv = *(const float4*)&Vs[c][tx * 4];
            float a[4] = {av.x, av.y, av.z, av.w};
            float bb[4] = {bv.x, bv.y, bv.z, bv.w};
#pragma unroll
            for (int i = 0; i < 4; i++)
#pragma unroll
                for (int j = 0; j < 4; j++)
                    acc[i][j] = fmaf(a[i], bb[j], acc[i][j]);
        }
        __syncthreads();
    }

    float* op = o + ((size_t)b * SEQ + qbase) * D_MODEL + h * HDIM;
#pragma unroll
    for (int i = 0; i < 4; i++) {
        const float inv = 1.f / l_i[i];
        const int r = ty * 4 + i;
#pragma unroll
        for (int j = 0; j < 4; j++)
            op[(size_t)r * D_MODEL + tx * 4 + j] = acc[i][j] * inv;
    }
}

// ---------------------------------------------------------------------------
extern "C" void kernel_launch(void* const* d_in, const int* in_sizes, int n_in,
                              void* d_out, int out_size)
{
    (void)in_sizes; (void)n_in; (void)out_size;
    const float* x  = (const float*)d_in[0];
    const float* Wq = (const float*)d_in[1];
    const float* bq = (const float*)d_in[2];
    const float* Wk = (const float*)d_in[3];
    const float* bk = (const float*)d_in[4];
    const float* Wv = (const float*)d_in[5];
    const float* bv = (const float*)d_in[6];
    const float* Wo = (const float*)d_in[7];
    const float* bo = (const float*)d_in[8];
    float* out = (float*)d_out;

    float *gq, *gk, *gv, *go;
    cudaGetSymbolAddress((void**)&gq, g_q);
    cudaGetSymbolAddress((void**)&gk, g_k);
    cudaGetSymbolAddress((void**)&gv, g_v);
    cudaGetSymbolAddress((void**)&go, g_o);

    dim3 gg(D_MODEL / BN, MROWS / BM);   // (8, 64)
    gemm_tf32_bias<<<gg, 256>>>(x, Wq, bq, gq, MROWS, D_MODEL, D_MODEL);
    gemm_tf32_bias<<<gg, 256>>>(x, Wk, bk, gk, MROWS, D_MODEL, D_MODEL);
    gemm_tf32_bias<<<gg, 256>>>(x, Wv, bv, gv, MROWS, D_MODEL, D_MODEL);

    dim3 ga(SEQ / 64, BATCH * HEADS);    // (32, 64)
    attn_causal<<<ga, 256>>>(gq, gk, gv, go);

    gemm_tf32_bias<<<gg, 256>>>(go, Wo, bo, out, MROWS, D_MODEL, D_MODEL);
}

// round 5
// speedup vs baseline: 1.7030x; 1.4985x over previous
#include <cuda_runtime.h>
#include <cuda_fp16.h>
#include <mma.h>
#include <cstddef>
#include <cstdint>

using namespace nvcuda;

#define D_MODEL 1024
#define SEQ     2048
#define BATCH   4
#define HEADS   16
#define HDIM    64
#define MROWS   (BATCH * SEQ)   /* 8192 */

// Scratch (alloc-free rule: __device__ globals)
__device__ float g_q[MROWS * D_MODEL];
__device__ float g_k[MROWS * D_MODEL];
__device__ float g_v[MROWS * D_MODEL];
__device__ float g_o[MROWS * D_MODEL];
__device__ __half g_xh[MROWS * D_MODEL];
__device__ __half g_oh[MROWS * D_MODEL];
__device__ __half g_wth[4 * D_MODEL * D_MODEL];   // transposed half weights

// ---------------------------------------------------------------------------
// cp.async helpers (sm_80 PTX, assembles for compute_103 baseline)
// ---------------------------------------------------------------------------
__device__ __forceinline__ uint32_t smem_u32(const void* p) {
    uint32_t a;
    asm("{ .reg .u64 t; cvta.to.shared.u64 t, %1; cvt.u32.u64 %0, t; }"
        : "=r"(a) : "l"(p));
    return a;
}
__device__ __forceinline__ void cp_async16(uint32_t dst, const void* src) {
    asm volatile("cp.async.cg.shared.global [%0], [%1], 16;"
                 :: "r"(dst), "l"(__cvta_generic_to_global(src)) : "memory");
}
__device__ __forceinline__ void cp_commit() {
    asm volatile("cp.async.commit_group;" ::: "memory");
}
template <int N>
__device__ __forceinline__ void cp_wait() {
    asm volatile("cp.async.wait_group %0;" :: "n"(N) : "memory");
}

// ---------------------------------------------------------------------------
// Converters
// ---------------------------------------------------------------------------
__global__ __launch_bounds__(256) void f2h(const float* __restrict__ in,
                                           __half* __restrict__ out, int n)
{
    const int i = (blockIdx.x * 256 + threadIdx.x) * 8;
    if (i < n) {
        float4 a = *(const float4*)(in + i);
        float4 b = *(const float4*)(in + i + 4);
        __half2 h[4];
        h[0] = __floats2half2_rn(a.x, a.y);
        h[1] = __floats2half2_rn(a.z, a.w);
        h[2] = __floats2half2_rn(b.x, b.y);
        h[3] = __floats2half2_rn(b.z, b.w);
        *(uint4*)(out + i) = *(uint4*)h;
    }
}

// W fp32 [K][N] -> WT half [N][K]
__global__ __launch_bounds__(256) void transpose_f2h(
    const float* __restrict__ in, __half* __restrict__ out)
{
    __shared__ float t[32][33];
    const int bx = blockIdx.x * 32, by = blockIdx.y * 32;
    const int x = threadIdx.x & 31, y0 = threadIdx.x >> 5;
#pragma unroll
    for (int i = 0; i < 32; i += 8)
        t[y0 + i][x] = in[(size_t)(by + y0 + i) * D_MODEL + bx + x];
    __syncthreads();
#pragma unroll
    for (int i = 0; i < 32; i += 8)
        out[(size_t)(bx + y0 + i) * D_MODEL + by + x] = __float2half(t[x][y0 + i]);
}

// ---------------------------------------------------------------------------
// fp16 tensor-core GEMM: C[M,N](fp32) = A[M,K](h) @ BT[N,K](h)^T + bias[N]
// 128x128x32 tile, cp.async double-buffered, 256 threads (8 warps, 4x2),
// warp tile 32x64 = 2x4 wmma m16n16k16 accumulators (fp32).
// ---------------------------------------------------------------------------
#define BM 128
#define BN 128
#define BKH 32            // K elements per stage
#define LDH 40            // smem row stride in halves (80B) -> conflict-free
#define TILE_H (128 * LDH)        // halves per operand tile (5120)
#define STAGE_B (2 * TILE_H * 2)  // bytes per stage (A+B) = 20480
#define GK 1024

__global__ __launch_bounds__(256) void gemm_h_bias(
    const __half* __restrict__ A, const __half* __restrict__ BT,
    const float* __restrict__ bias, float* __restrict__ C)
{
    __shared__ __align__(16) char sm[2 * STAGE_B];   // 40960 B
    const uint32_t sb = smem_u32(sm);

    const int tid  = threadIdx.x;
    const int wid  = tid >> 5;
    const int wm   = wid >> 1;        // 0..3
    const int wn   = wid & 1;         // 0..1
    const int row0 = blockIdx.y * BM;
    const int col0 = blockIdx.x * BN;

    // --- Seed accumulators with bias via broadcast tile (overlaid on stage 1,
    //     which is first written only at loop iteration 0's prefetch). ---
    float* BiasF = (float*)(sm + STAGE_B);   // 16 x 128 floats = 8192 B
    for (int idx = tid; idx < 16 * BN; idx += 256)
        BiasF[idx] = bias[col0 + (idx & 127)];
    __syncthreads();

    wmma::fragment<wmma::accumulator, 16, 16, 16, float> acc[2][4];
#pragma unroll
    for (int i = 0; i < 2; i++)
#pragma unroll
        for (int j = 0; j < 4; j++)
            wmma::load_matrix_sync(acc[i][j], &BiasF[wn * 64 + j * 16],
                                   BN, wmma::mem_row_major);
    __syncthreads();

    // chunk mapping: 512 16B-chunks per operand tile; thread does 2 of each.
    const int r0 = tid >> 2;            // 0..63 (+64)
    const int c0 = (tid & 3) * 8;       // half offset 0,8,16,24

    auto load_stage = [&](int k0, int s) {
        const uint32_t abase = sb + s * STAGE_B;
        const uint32_t bbase = abase + TILE_H * 2;
#pragma unroll
        for (int i = 0; i < 2; i++) {
            const int r = r0 + i * 64;
            cp_async16(abase + (r * LDH + c0) * 2,
                       A + (size_t)(row0 + r) * GK + k0 + c0);
        }
#pragma unroll
        for (int i = 0; i < 2; i++) {
            const int r = r0 + i * 64;
            cp_async16(bbase + (r * LDH + c0) * 2,
                       BT + (size_t)(col0 + r) * GK + k0 + c0);
        }
        cp_commit();
    };

    load_stage(0, 0);

    const int NIT = GK / BKH;   // 32
    for (int it = 0; it < NIT; it++) {
        const int s = it & 1;
        if (it + 1 < NIT) { load_stage((it + 1) * BKH, s ^ 1); cp_wait<1>(); }
        else              { cp_wait<0>(); }
        __syncthreads();

        const __half* smA = (const __half*)(sm + s * STAGE_B);
        const __half* smB = smA + TILE_H;

#pragma unroll
        for (int kk = 0; kk < BKH; kk += 16) {
            wmma::fragment<wmma::matrix_a, 16, 16, 16, __half, wmma::row_major> af[2];
            wmma::fragment<wmma::matrix_b, 16, 16, 16, __half, wmma::col_major> bf[4];
#pragma unroll
            for (int i = 0; i < 2; i++)
                wmma::load_matrix_sync(af[i], smA + (wm * 32 + i * 16) * LDH + kk, LDH);
#pragma unroll
            for (int j = 0; j < 4; j++)
                wmma::load_matrix_sync(bf[j], smB + (wn * 64 + j * 16) * LDH + kk, LDH);
#pragma unroll
            for (int i = 0; i < 2; i++)
#pragma unroll
                for (int j = 0; j < 4; j++)
                    wmma::mma_sync(acc[i][j], af[i], bf[j], acc[i][j]);
        }
        __syncthreads();
    }

    // Epilogue (bias already inside acc)
#pragma unroll
    for (int i = 0; i < 2; i++)
#pragma unroll
        for (int j = 0; j < 4; j++) {
            float* cp = &C[(size_t)(row0 + wm * 32 + i * 16) * D_MODEL +
                           col0 + wn * 64 + j * 16];
            wmma::store_matrix_sync(cp, acc[i][j], D_MODEL, wmma::mem_row_major);
        }
}

// ---------------------------------------------------------------------------
// Causal flash attention, fp32 (unchanged, known-correct)
// ---------------------------------------------------------------------------
__global__ __launch_bounds__(256) void attn_causal(
    const float* __restrict__ q, const float* __restrict__ k,
    const float* __restrict__ v, float* __restrict__ o)
{
    __shared__ float Qs[64][64];
    __shared__ float KPs[64][64];
    __shared__ float Vs[64][64];

    const int tid = threadIdx.x;
    const int tx  = tid & 15;
    const int ty  = tid >> 4;
    const int qt  = blockIdx.x;
    const int bh  = blockIdx.y;
    const int b   = bh >> 4;
    const int h   = bh & 15;
    const int qbase = qt * 64;

    const float* qp = q + ((size_t)b * SEQ + qbase) * D_MODEL + h * HDIM;

    for (int idx = tid; idx < 64 * 64; idx += 256) {
        const int r = idx >> 6, d = idx & 63;
        Qs[d][r] = qp[(size_t)r * D_MODEL + d] * 0.125f;
    }

    float m_i[4], l_i[4], acc[4][4];
#pragma unroll
    for (int i = 0; i < 4; i++) {
        m_i[i] = -1e30f;
        l_i[i] = 0.f;
#pragma unroll
        for (int j = 0; j < 4; j++) acc[i][j] = 0.f;
    }
    __syncthreads();

    const int nkt = qt + 1;
    for (int kt = 0; kt < nkt; kt++) {
        const int kbase = kt * 64;
        const float* kp = k + ((size_t)b * SEQ + kbase) * D_MODEL + h * HDIM;
        const float* vp = v + ((size_t)b * SEQ + kbase) * D_MODEL + h * HDIM;
        for (int idx = tid; idx < 64 * 64; idx += 256) {
            const int c = idx >> 6, d = idx & 63;
            KPs[d][c] = kp[(size_t)c * D_MODEL + d];
            Vs[c][d]  = vp[(size_t)c * D_MODEL + d];
        }
        __syncthreads();

        float s[4][4];
#pragma unroll
        for (int i = 0; i < 4; i++)
#pragma unroll
            for (int j = 0; j < 4; j++) s[i][j] = 0.f;

#pragma unroll 8
        for (int d = 0; d < 64; d++) {
            float4 av = *(const float4*)&Qs[d][ty * 4];
            float4 bv = *(const float4*)&KPs[d][tx * 4];
            float a[4] = {av.x, av.y, av.z, av.w};
            float bb[4] = {bv.x, bv.y, bv.z, bv.w};
#pragma unroll
            for (int i = 0; i < 4; i++)
#pragma unroll
                for (int j = 0; j < 4; j++)
                    s[i][j] = fmaf(a[i], bb[j], s[i][j]);
        }

        if (kt == qt) {
#pragma unroll
            for (int i = 0; i < 4; i++) {
                const int r = ty * 4 + i;
#pragma unroll
                for (int j = 0; j < 4; j++) {
                    const int c = tx * 4 + j;
                    if (c > r) s[i][j] = -1e30f;
                }
            }
        }

#pragma unroll
        for (int i = 0; i < 4; i++) {
            float mx = fmaxf(fmaxf(s[i][0], s[i][1]), fmaxf(s[i][2], s[i][3]));
#pragma unroll
            for (int off = 8; off >= 1; off >>= 1)
                mx = fmaxf(mx, __shfl_xor_sync(0xffffffffu, mx, off));
            const float mnew  = fmaxf(m_i[i], mx);
            const float scale = __expf(m_i[i] - mnew);
            float rs = 0.f;
#pragma unroll
            for (int j = 0; j < 4; j++) {
                s[i][j] = __expf(s[i][j] - mnew);
                rs += s[i][j];
            }
#pragma unroll
            for (int off = 8; off >= 1; off >>= 1)
                rs += __shfl_xor_sync(0xffffffffu, rs, off);
            l_i[i] = l_i[i] * scale + rs;
            m_i[i] = mnew;
#pragma unroll
            for (int j = 0; j < 4; j++) acc[i][j] *= scale;
        }

        __syncthreads();
#pragma unroll
        for (int i = 0; i < 4; i++)
#pragma unroll
            for (int j = 0; j < 4; j++)
                KPs[tx * 4 + j][ty * 4 + i] = s[i][j];
        __syncthreads();

#pragma unroll 8
        for (int c = 0; c < 64; c++) {
            float4 av = *(const float4*)&KPs[c][ty * 4];
            float4 bv = *(const float4*)&Vs[c][tx * 4];
            float a[4] = {av.x, av.y, av.z, av.w};
            float bb[4] = {bv.x, bv.y, bv.z, bv.w};
#pragma unroll
            for (int i = 0; i < 4; i++)
#pragma unroll
                for (int j = 0; j < 4; j++)
                    acc[i][j] = fmaf(a[i], bb[j], acc[i][j]);
        }
        __syncthreads();
    }

    float* op = o + ((size_t)b * SEQ + qbase) * D_MODEL + h * HDIM;
#pragma unroll
    for (int i = 0; i < 4; i++) {
        const float inv = 1.f / l_i[i];
        const int r = ty * 4 + i;
#pragma unroll
        for (int j = 0; j < 4; j++)
            op[(size_t)r * D_MODEL + tx * 4 + j] = acc[i][j] * inv;
    }
}

// ---------------------------------------------------------------------------
extern "C" void kernel_launch(void* const* d_in, const int* in_sizes, int n_in,
                              void* d_out, int out_size)
{
    (void)in_sizes; (void)n_in; (void)out_size;
    const float* x  = (const float*)d_in[0];
    const float* Wq = (const float*)d_in[1];
    const float* bq = (const float*)d_in[2];
    const float* Wk = (const float*)d_in[3];
    const float* bk = (const float*)d_in[4];
    const float* Wv = (const float*)d_in[5];
    const float* bv = (const float*)d_in[6];
    const float* Wo = (const float*)d_in[7];
    const float* bo = (const float*)d_in[8];
    float* out = (float*)d_out;

    float *gq, *gk, *gv, *go;
    __half *gxh, *goh, *gwth;
    cudaGetSymbolAddress((void**)&gq, g_q);
    cudaGetSymbolAddress((void**)&gk, g_k);
    cudaGetSymbolAddress((void**)&gv, g_v);
    cudaGetSymbolAddress((void**)&go, g_o);
    cudaGetSymbolAddress((void**)&gxh, g_xh);
    cudaGetSymbolAddress((void**)&goh, g_oh);
    cudaGetSymbolAddress((void**)&gwth, g_wth);
    __half* wtq = gwth;
    __half* wtk = gwth + 1 * D_MODEL * D_MODEL;
    __half* wtv = gwth + 2 * D_MODEL * D_MODEL;
    __half* wto = gwth + 3 * D_MODEL * D_MODEL;

    const int NELEM = MROWS * D_MODEL;

    dim3 gt(32, 32);
    transpose_f2h<<<gt, 256>>>(Wq, wtq);
    transpose_f2h<<<gt, 256>>>(Wk, wtk);
    transpose_f2h<<<gt, 256>>>(Wv, wtv);
    transpose_f2h<<<gt, 256>>>(Wo, wto);
    f2h<<<NELEM / (256 * 8), 256>>>(x, gxh, NELEM);

    dim3 gg(D_MODEL / BN, MROWS / BM);   // (8, 64)
    gemm_h_bias<<<gg, 256>>>(gxh, wtq, bq, gq);
    gemm_h_bias<<<gg, 256>>>(gxh, wtk, bk, gk);
    gemm_h_bias<<<gg, 256>>>(gxh, wtv, bv, gv);

    dim3 ga(SEQ / 64, BATCH * HEADS);    // (32, 64)
    attn_causal<<<ga, 256>>>(gq, gk, gv, go);

    f2h<<<NELEM / (256 * 8), 256>>>(go, goh, NELEM);
    gemm_h_bias<<<gg, 256>>>(goh, wto, bo, out);
}

// round 7
// speedup vs baseline: 5.2568x; 3.0867x over previous
#include <cuda_runtime.h>
#include <cuda_fp16.h>
#include <mma.h>
#include <cstddef>
#include <cstdint>

using namespace nvcuda;

#define D_MODEL 1024
#define SEQ     2048
#define BATCH   4
#define HEADS   16
#define HDIM    64
#define MROWS   (BATCH * SEQ)   /* 8192 */

// Scratch (alloc-free rule: __device__ globals)
__device__ float  g_q[MROWS * D_MODEL];
__device__ float  g_k[MROWS * D_MODEL];
__device__ float  g_v[MROWS * D_MODEL];
__device__ __half g_qh[MROWS * D_MODEL];
__device__ __half g_kh[MROWS * D_MODEL];
__device__ __half g_vh[MROWS * D_MODEL];
__device__ __half g_xh[MROWS * D_MODEL];
__device__ __half g_oh[MROWS * D_MODEL];
__device__ __half g_wth[4 * D_MODEL * D_MODEL];   // transposed half weights

// ---------------------------------------------------------------------------
// cp.async helpers
// ---------------------------------------------------------------------------
__device__ __forceinline__ uint32_t smem_u32(const void* p) {
    uint32_t a;
    asm("{ .reg .u64 t; cvta.to.shared.u64 t, %1; cvt.u32.u64 %0, t; }"
        : "=r"(a) : "l"(p));
    return a;
}
__device__ __forceinline__ void cp_async16(uint32_t dst, const void* src) {
    asm volatile("cp.async.cg.shared.global [%0], [%1], 16;"
                 :: "r"(dst), "l"(__cvta_generic_to_global(src)) : "memory");
}
__device__ __forceinline__ void cp_commit() {
    asm volatile("cp.async.commit_group;" ::: "memory");
}
template <int N>
__device__ __forceinline__ void cp_wait() {
    asm volatile("cp.async.wait_group %0;" :: "n"(N) : "memory");
}

// ---------------------------------------------------------------------------
// Converters
// ---------------------------------------------------------------------------
__global__ __launch_bounds__(256) void f2h(const float* __restrict__ in,
                                           __half* __restrict__ out, int n)
{
    const int i = (blockIdx.x * 256 + threadIdx.x) * 8;
    if (i < n) {
        float4 a = *(const float4*)(in + i);
        float4 b = *(const float4*)(in + i + 4);
        __half2 h[4];
        h[0] = __floats2half2_rn(a.x, a.y);
        h[1] = __floats2half2_rn(a.z, a.w);
        h[2] = __floats2half2_rn(b.x, b.y);
        h[3] = __floats2half2_rn(b.z, b.w);
        *(uint4*)(out + i) = *(uint4*)h;
    }
}

// W fp32 [K][N] -> WT half [N][K]
__global__ __launch_bounds__(256) void transpose_f2h(
    const float* __restrict__ in, __half* __restrict__ out)
{
    __shared__ float t[32][33];
    const int bx = blockIdx.x * 32, by = blockIdx.y * 32;
    const int x = threadIdx.x & 31, y0 = threadIdx.x >> 5;
#pragma unroll
    for (int i = 0; i < 32; i += 8)
        t[y0 + i][x] = in[(size_t)(by + y0 + i) * D_MODEL + bx + x];
    __syncthreads();
#pragma unroll
    for (int i = 0; i < 32; i += 8)
        out[(size_t)(bx + y0 + i) * D_MODEL + by + x] = __float2half(t[x][y0 + i]);
}

// ---------------------------------------------------------------------------
// fp16 tensor-core GEMM (unchanged from round 5, proven)
// ---------------------------------------------------------------------------
#define BM 128
#define BN 128
#define BKH 32
#define LDH 40
#define TILE_H (128 * LDH)
#define STAGE_B (2 * TILE_H * 2)
#define GK 1024

__global__ __launch_bounds__(256) void gemm_h_bias(
    const __half* __restrict__ A, const __half* __restrict__ BT,
    const float* __restrict__ bias, float* __restrict__ C)
{
    __shared__ __align__(16) char sm[2 * STAGE_B];
    const uint32_t sb = smem_u32(sm);

    const int tid  = threadIdx.x;
    const int wid  = tid >> 5;
    const int wm   = wid >> 1;
    const int wn   = wid & 1;
    const int row0 = blockIdx.y * BM;
    const int col0 = blockIdx.x * BN;

    float* BiasF = (float*)(sm + STAGE_B);
    for (int idx = tid; idx < 16 * BN; idx += 256)
        BiasF[idx] = bias[col0 + (idx & 127)];
    __syncthreads();

    wmma::fragment<wmma::accumulator, 16, 16, 16, float> acc[2][4];
#pragma unroll
    for (int i = 0; i < 2; i++)
#pragma unroll
        for (int j = 0; j < 4; j++)
            wmma::load_matrix_sync(acc[i][j], &BiasF[wn * 64 + j * 16],
                                   BN, wmma::mem_row_major);
    __syncthreads();

    const int r0 = tid >> 2;
    const int c0 = (tid & 3) * 8;

    auto load_stage = [&](int k0, int s) {
        const uint32_t abase = sb + s * STAGE_B;
        const uint32_t bbase = abase + TILE_H * 2;
#pragma unroll
        for (int i = 0; i < 2; i++) {
            const int r = r0 + i * 64;
            cp_async16(abase + (r * LDH + c0) * 2,
                       A + (size_t)(row0 + r) * GK + k0 + c0);
        }
#pragma unroll
        for (int i = 0; i < 2; i++) {
            const int r = r0 + i * 64;
            cp_async16(bbase + (r * LDH + c0) * 2,
                       BT + (size_t)(col0 + r) * GK + k0 + c0);
        }
        cp_commit();
    };

    load_stage(0, 0);

    const int NIT = GK / BKH;
    for (int it = 0; it < NIT; it++) {
        const int s = it & 1;
        if (it + 1 < NIT) { load_stage((it + 1) * BKH, s ^ 1); cp_wait<1>(); }
        else              { cp_wait<0>(); }
        __syncthreads();

        const __half* smA = (const __half*)(sm + s * STAGE_B);
        const __half* smB = smA + TILE_H;

#pragma unroll
        for (int kk = 0; kk < BKH; kk += 16) {
            wmma::fragment<wmma::matrix_a, 16, 16, 16, __half, wmma::row_major> af[2];
            wmma::fragment<wmma::matrix_b, 16, 16, 16, __half, wmma::col_major> bf[4];
#pragma unroll
            for (int i = 0; i < 2; i++)
                wmma::load_matrix_sync(af[i], smA + (wm * 32 + i * 16) * LDH + kk, LDH);
#pragma unroll
            for (int j = 0; j < 4; j++)
                wmma::load_matrix_sync(bf[j], smB + (wn * 64 + j * 16) * LDH + kk, LDH);
#pragma unroll
            for (int i = 0; i < 2; i++)
#pragma unroll
                for (int j = 0; j < 4; j++)
                    wmma::mma_sync(acc[i][j], af[i], bf[j], acc[i][j]);
        }
        __syncthreads();
    }

#pragma unroll
    for (int i = 0; i < 2; i++)
#pragma unroll
        for (int j = 0; j < 4; j++) {
            float* cp = &C[(size_t)(row0 + wm * 32 + i * 16) * D_MODEL +
                           col0 + wn * 64 + j * 16];
            wmma::store_matrix_sync(cp, acc[i][j], D_MODEL, wmma::mem_row_major);
        }
}

// ---------------------------------------------------------------------------
// fp16 wmma causal flash attention.
// Block = (b, h, 64-row q-tile), 256 threads = 8 warps (4x2 over m x n).
// Smem (dynamic, 73728 B):
//   Qh/Kh/Vh/Ph : half [64][72]
//   Sf/Os       : float [64][72]
// 1/8 scale folded into softmax read (fp32). O accumulated fp32 in smem.
// ---------------------------------------------------------------------------
#define AT_LD 72
#define ATT_SMEM (4 * 64 * AT_LD * 2 + 2 * 64 * AT_LD * 4)   /* 73728 */

__global__ __launch_bounds__(256) void attn_wmma(
    const __half* __restrict__ q, const __half* __restrict__ k,
    const __half* __restrict__ v, __half* __restrict__ o)
{
    extern __shared__ __align__(16) char sm[];
    __half* Qh = (__half*)sm;
    __half* Kh = Qh + 64 * AT_LD;
    __half* Vh = Kh + 64 * AT_LD;
    __half* Ph = Vh + 64 * AT_LD;
    float*  Sf = (float*)(Ph + 64 * AT_LD);
    float*  Os = Sf + 64 * AT_LD;

    const int tid = threadIdx.x;
    const int wid = tid >> 5;
    const int wm  = wid & 3;        // 16-row stripe
    const int wn  = wid >> 2;       // 32-col stripe
    const int qt  = blockIdx.x;
    const int bh  = blockIdx.y;
    const int b   = bh >> 4;
    const int h   = bh & 15;
    const int qbase = qt * 64;

    // softmax ownership: 4 threads per row
    const int srow = tid >> 2;
    const int sseg = (tid & 3) * 16;

    const __half* qp = q + ((size_t)b * SEQ + qbase) * D_MODEL + h * HDIM;

    // Load Q tile (raw copy, 8 halves per 16B chunk; 512 chunks)
#pragma unroll
    for (int i = 0; i < 2; i++) {
        const int chunk = tid + i * 256;
        const int r = chunk >> 3, c8 = (chunk & 7) * 8;
        *(uint4*)&Qh[r * AT_LD + c8] = *(const uint4*)(qp + (size_t)r * D_MODEL + c8);
    }
    // Zero O accumulator
    for (int idx = tid; idx < 64 * AT_LD; idx += 256) Os[idx] = 0.f;

    float m_i = -1e30f, l_i = 0.f;
    __syncthreads();

    for (int kt = 0; kt <= qt; kt++) {
        const size_t krow = (size_t)b * SEQ + kt * 64;
        const __half* kp = k + krow * D_MODEL + h * HDIM;
        const __half* vp = v + krow * D_MODEL + h * HDIM;
#pragma unroll
        for (int i = 0; i < 2; i++) {
            const int chunk = tid + i * 256;
            const int r = chunk >> 3, c8 = (chunk & 7) * 8;
            *(uint4*)&Kh[r * AT_LD + c8] = *(const uint4*)(kp + (size_t)r * D_MODEL + c8);
            *(uint4*)&Vh[r * AT_LD + c8] = *(const uint4*)(vp + (size_t)r * D_MODEL + c8);
        }
        __syncthreads();

        // ---- S = Q @ K^T ----
        {
            wmma::fragment<wmma::accumulator, 16, 16, 16, float> sacc[2];
#pragma unroll
            for (int j = 0; j < 2; j++) wmma::fill_fragment(sacc[j], 0.f);
#pragma unroll
            for (int kk = 0; kk < 64; kk += 16) {
                wmma::fragment<wmma::matrix_a, 16, 16, 16, __half, wmma::row_major> af;
                wmma::load_matrix_sync(af, Qh + (wm * 16) * AT_LD + kk, AT_LD);
#pragma unroll
                for (int j = 0; j < 2; j++) {
                    wmma::fragment<wmma::matrix_b, 16, 16, 16, __half, wmma::col_major> bf;
                    wmma::load_matrix_sync(bf, Kh + (wn * 32 + j * 16) * AT_LD + kk, AT_LD);
                    wmma::mma_sync(sacc[j], af, bf, sacc[j]);
                }
            }
#pragma unroll
            for (int j = 0; j < 2; j++)
                wmma::store_matrix_sync(Sf + (wm * 16) * AT_LD + wn * 32 + j * 16,
                                        sacc[j], AT_LD, wmma::mem_row_major);
        }
        __syncthreads();

        // ---- online softmax (SIMT, 4 threads/row) ----
        {
            float x[16];
#pragma unroll
            for (int j = 0; j < 16; j++)
                x[j] = Sf[srow * AT_LD + sseg + j] * 0.125f;
            if (kt == qt) {
#pragma unroll
                for (int j = 0; j < 16; j++)
                    if (sseg + j > srow) x[j] = -1e30f;
            }
            float mx = x[0];
#pragma unroll
            for (int j = 1; j < 16; j++) mx = fmaxf(mx, x[j]);
            mx = fmaxf(mx, __shfl_xor_sync(0xffffffffu, mx, 1));
            mx = fmaxf(mx, __shfl_xor_sync(0xffffffffu, mx, 2));
            const float mnew  = fmaxf(m_i, mx);
            const float scale = __expf(m_i - mnew);
            float rs = 0.f;
#pragma unroll
            for (int j = 0; j < 16; j++) {
                x[j] = __expf(x[j] - mnew);
                rs += x[j];
            }
            rs += __shfl_xor_sync(0xffffffffu, rs, 1);
            rs += __shfl_xor_sync(0xffffffffu, rs, 2);
            l_i = l_i * scale + rs;
            m_i = mnew;
            // rescale O row segment, write P
#pragma unroll
            for (int j = 0; j < 16; j++)
                Os[srow * AT_LD + sseg + j] *= scale;
#pragma unroll
            for (int j = 0; j < 16; j += 2)
                *(__half2*)&Ph[srow * AT_LD + sseg + j] =
                    __floats2half2_rn(x[j], x[j + 1]);
        }
        __syncthreads();

        // ---- O += P @ V ----
        {
            wmma::fragment<wmma::accumulator, 16, 16, 16, float> oacc[2];
#pragma unroll
            for (int j = 0; j < 2; j++)
                wmma::load_matrix_sync(oacc[j],
                    Os + (wm * 16) * AT_LD + wn * 32 + j * 16, AT_LD,
                    wmma::mem_row_major);
#pragma unroll
            for (int kk = 0; kk < 64; kk += 16) {
                wmma::fragment<wmma::matrix_a, 16, 16, 16, __half, wmma::row_major> af;
                wmma::load_matrix_sync(af, Ph + (wm * 16) * AT_LD + kk, AT_LD);
#pragma unroll
                for (int j = 0; j < 2; j++) {
                    wmma::fragment<wmma::matrix_b, 16, 16, 16, __half, wmma::row_major> bf;
                    wmma::load_matrix_sync(bf, Vh + kk * AT_LD + wn * 32 + j * 16, AT_LD);
                    wmma::mma_sync(oacc[j], af, bf, oacc[j]);
                }
            }
#pragma unroll
            for (int j = 0; j < 2; j++)
                wmma::store_matrix_sync(Os + (wm * 16) * AT_LD + wn * 32 + j * 16,
                                        oacc[j], AT_LD, wmma::mem_row_major);
        }
        __syncthreads();
    }

    // Epilogue: normalize, write half
    {
        const float inv = 1.f / l_i;
        __half* op = o + ((size_t)b * SEQ + qbase + srow) * D_MODEL + h * HDIM;
#pragma unroll
        for (int j = 0; j < 16; j += 2)
            *(__half2*)&op[sseg + j] = __floats2half2_rn(
                Os[srow * AT_LD + sseg + j] * inv,
                Os[srow * AT_LD + sseg + j + 1] * inv);
    }
}

// ---------------------------------------------------------------------------
extern "C" void kernel_launch(void* const* d_in, const int* in_sizes, int n_in,
                              void* d_out, int out_size)
{
    (void)in_sizes; (void)n_in; (void)out_size;
    const float* x  = (const float*)d_in[0];
    const float* Wq = (const float*)d_in[1];
    const float* bq = (const float*)d_in[2];
    const float* Wk = (const float*)d_in[3];
    const float* bk = (const float*)d_in[4];
    const float* Wv = (const float*)d_in[5];
    const float* bv = (const float*)d_in[6];
    const float* Wo = (const float*)d_in[7];
    const float* bo = (const float*)d_in[8];
    float* out = (float*)d_out;

    float *gq, *gk, *gv;
    __half *gqh, *gkh, *gvh, *gxh, *goh, *gwth;
    cudaGetSymbolAddress((void**)&gq, g_q);
    cudaGetSymbolAddress((void**)&gk, g_k);
    cudaGetSymbolAddress((void**)&gv, g_v);
    cudaGetSymbolAddress((void**)&gqh, g_qh);
    cudaGetSymbolAddress((void**)&gkh, g_kh);
    cudaGetSymbolAddress((void**)&gvh, g_vh);
    cudaGetSymbolAddress((void**)&gxh, g_xh);
    cudaGetSymbolAddress((void**)&goh, g_oh);
    cudaGetSymbolAddress((void**)&gwth, g_wth);
    __half* wtq = gwth;
    __half* wtk = gwth + 1 * D_MODEL * D_MODEL;
    __half* wtv = gwth + 2 * D_MODEL * D_MODEL;
    __half* wto = gwth + 3 * D_MODEL * D_MODEL;

    const int NELEM = MROWS * D_MODEL;

    cudaFuncSetAttribute(attn_wmma,
                         cudaFuncAttributeMaxDynamicSharedMemorySize, ATT_SMEM);

    dim3 gt(32, 32);
    transpose_f2h<<<gt, 256>>>(Wq, wtq);
    transpose_f2h<<<gt, 256>>>(Wk, wtk);
    transpose_f2h<<<gt, 256>>>(Wv, wtv);
    transpose_f2h<<<gt, 256>>>(Wo, wto);
    f2h<<<NELEM / (256 * 8), 256>>>(x, gxh, NELEM);

    dim3 gg(D_MODEL / BN, MROWS / BM);   // (8, 64)
    gemm_h_bias<<<gg, 256>>>(gxh, wtq, bq, gq);
    gemm_h_bias<<<gg, 256>>>(gxh, wtk, bk, gk);
    gemm_h_bias<<<gg, 256>>>(gxh, wtv, bv, gv);
    f2h<<<NELEM / (256 * 8), 256>>>(gq, gqh, NELEM);
    f2h<<<NELEM / (256 * 8), 256>>>(gk, gkh, NELEM);
    f2h<<<NELEM / (256 * 8), 256>>>(gv, gvh, NELEM);

    dim3 ga(SEQ / 64, BATCH * HEADS);    // (32, 64)
    attn_wmma<<<ga, 256, ATT_SMEM>>>(gqh, gkh, gvh, goh);

    gemm_h_bias<<<gg, 256>>>(goh, wto, bo, out);
}

// round 9
// speedup vs baseline: 5.7224x; 1.0886x over previous
#include <cuda_runtime.h>
#include <cuda_fp16.h>
#include <mma.h>
#include <cstddef>
#include <cstdint>

using namespace nvcuda;

#define D_MODEL 1024
#define SEQ     2048
#define BATCH   4
#define HEADS   16
#define HDIM    64
#define MROWS   (BATCH * SEQ)   /* 8192 */

// Scratch (alloc-free rule: __device__ globals)
__device__ __half g_qh[MROWS * D_MODEL];
__device__ __half g_kh[MROWS * D_MODEL];
__device__ __half g_vh[MROWS * D_MODEL];
__device__ __half g_xh[MROWS * D_MODEL];
__device__ __half g_oh[MROWS * D_MODEL];
__device__ __half g_wth[4 * D_MODEL * D_MODEL];   // transposed half weights (q,k,v,o)

// ---------------------------------------------------------------------------
// cp.async helpers
// ---------------------------------------------------------------------------
__device__ __forceinline__ uint32_t smem_u32(const void* p) {
    uint32_t a;
    asm("{ .reg .u64 t; cvta.to.shared.u64 t, %1; cvt.u32.u64 %0, t; }"
        : "=r"(a) : "l"(p));
    return a;
}
__device__ __forceinline__ void cp_async16(uint32_t dst, const void* src) {
    asm volatile("cp.async.cg.shared.global [%0], [%1], 16;"
                 :: "r"(dst), "l"(__cvta_generic_to_global(src)) : "memory");
}
__device__ __forceinline__ void cp_commit() {
    asm volatile("cp.async.commit_group;" ::: "memory");
}
template <int N>
__device__ __forceinline__ void cp_wait() {
    asm volatile("cp.async.wait_group %0;" :: "n"(N) : "memory");
}

// ---------------------------------------------------------------------------
// Converters
// ---------------------------------------------------------------------------
__global__ __launch_bounds__(256) void f2h(const float* __restrict__ in,
                                           __half* __restrict__ out, int n)
{
    const int i = (blockIdx.x * 256 + threadIdx.x) * 8;
    if (i < n) {
        float4 a = *(const float4*)(in + i);
        float4 b = *(const float4*)(in + i + 4);
        __half2 h[4];
        h[0] = __floats2half2_rn(a.x, a.y);
        h[1] = __floats2half2_rn(a.z, a.w);
        h[2] = __floats2half2_rn(b.x, b.y);
        h[3] = __floats2half2_rn(b.z, b.w);
        *(uint4*)(out + i) = *(uint4*)h;
    }
}

// 4 weight transposes in one launch: W fp32 [K][N] -> WT half [N][K], z selects.
__global__ __launch_bounds__(256) void transpose_f2h4(
    const float* __restrict__ W0, const float* __restrict__ W1,
    const float* __restrict__ W2, const float* __restrict__ W3,
    __half* __restrict__ outbase)
{
    __shared__ float t[32][33];
    const int z = blockIdx.z;
    const float* in = (z == 0) ? W0 : (z == 1) ? W1 : (z == 2) ? W2 : W3;
    __half* out = outbase + (size_t)z * D_MODEL * D_MODEL;
    const int bx = blockIdx.x * 32, by = blockIdx.y * 32;
    const int x = threadIdx.x & 31, y0 = threadIdx.x >> 5;
#pragma unroll
    for (int i = 0; i < 32; i += 8)
        t[y0 + i][x] = in[(size_t)(by + y0 + i) * D_MODEL + bx + x];
    __syncthreads();
#pragma unroll
    for (int i = 0; i < 32; i += 8)
        out[(size_t)(bx + y0 + i) * D_MODEL + by + x] = __float2half(t[x][y0 + i]);
}

// ---------------------------------------------------------------------------
// fp16 tensor-core GEMM: C = A[M,K] @ BT[N,K]^T + bias
// 128x128x32 tile, cp.async double-buffered, 256 threads (8 warps, 4x2).
// OH=true : N=3072 fused QKV, writes half to H0/H1/H2 (seg by global col).
// OH=false: N=1024, writes fp32 to Cf.
// Epilogue goes through per-warp smem staging (reuses pipeline smem).
// ---------------------------------------------------------------------------
#define BM 128
#define BN 128
#define BKH 32
#define LDH 40
#define TILE_H (128 * LDH)
#define STAGE_B (2 * TILE_H * 2)
#define GK 1024

template <bool OH>
__global__ __launch_bounds__(256) void gemm_h(
    const __half* __restrict__ A, const __half* __restrict__ BT,
    const float* __restrict__ bias0, const float* __restrict__ bias1,
    const float* __restrict__ bias2,
    float* __restrict__ Cf,
    __half* __restrict__ H0, __half* __restrict__ H1, __half* __restrict__ H2)
{
    __shared__ __align__(16) char sm[2 * STAGE_B];   // 40960 B
    const uint32_t sb = smem_u32(sm);

    const int tid   = threadIdx.x;
    const int wid   = tid >> 5;
    const int lane  = tid & 31;
    const int wm    = wid >> 1;
    const int wn    = wid & 1;
    const int row0  = blockIdx.y * BM;
    const int col0g = blockIdx.x * BN;          // global col (0..3071 for QKV)
    const int seg   = col0g >> 10;
    const int colL  = col0g & 1023;             // col within output buffer
    const float* bias = (seg == 0) ? bias0 : (seg == 1) ? bias1 : bias2;
    __half* Hout      = (seg == 0) ? H0    : (seg == 1) ? H1    : H2;

    wmma::fragment<wmma::accumulator, 16, 16, 16, float> acc[2][4];
#pragma unroll
    for (int i = 0; i < 2; i++)
#pragma unroll
        for (int j = 0; j < 4; j++) wmma::fill_fragment(acc[i][j], 0.f);

    const int r0 = tid >> 2;
    const int c0 = (tid & 3) * 8;

    auto load_stage = [&](int k0, int s) {
        const uint32_t abase = sb + s * STAGE_B;
        const uint32_t bbase = abase + TILE_H * 2;
#pragma unroll
        for (int i = 0; i < 2; i++) {
            const int r = r0 + i * 64;
            cp_async16(abase + (r * LDH + c0) * 2,
                       A + (size_t)(row0 + r) * GK + k0 + c0);
        }
#pragma unroll
        for (int i = 0; i < 2; i++) {
            const int r = r0 + i * 64;
            cp_async16(bbase + (r * LDH + c0) * 2,
                       BT + (size_t)(col0g + r) * GK + k0 + c0);
        }
        cp_commit();
    };

    load_stage(0, 0);

    const int NIT = GK / BKH;   // 32
    for (int it = 0; it < NIT; it++) {
        const int s = it & 1;
        if (it + 1 < NIT) { load_stage((it + 1) * BKH, s ^ 1); cp_wait<1>(); }
        else              { cp_wait<0>(); }
        __syncthreads();

        const __half* smA = (const __half*)(sm + s * STAGE_B);
        const __half* smB = smA + TILE_H;

#pragma unroll
        for (int kk = 0; kk < BKH; kk += 16) {
            wmma::fragment<wmma::matrix_a, 16, 16, 16, __half, wmma::row_major> af[2];
            wmma::fragment<wmma::matrix_b, 16, 16, 16, __half, wmma::col_major> bf[4];
#pragma unroll
            for (int i = 0; i < 2; i++)
                wmma::load_matrix_sync(af[i], smA + (wm * 32 + i * 16) * LDH + kk, LDH);
#pragma unroll
            for (int j = 0; j < 4; j++)
                wmma::load_matrix_sync(bf[j], smB + (wn * 64 + j * 16) * LDH + kk, LDH);
#pragma unroll
            for (int i = 0; i < 2; i++)
#pragma unroll
                for (int j = 0; j < 4; j++)
                    wmma::mma_sync(acc[i][j], af[i], bf[j], acc[i][j]);
        }
        __syncthreads();
    }

    // ---- Epilogue via per-warp staging (4KB each, reuses pipeline smem) ----
    float* Stg = (float*)sm + wid * 16 * 64;
    const int cb = wn * 64;                 // col within tile
    const float bx = bias[colL + cb + lane * 2];
    const float by = bias[colL + cb + lane * 2 + 1];
#pragma unroll
    for (int i = 0; i < 2; i++) {
#pragma unroll
        for (int j = 0; j < 4; j++)
            wmma::store_matrix_sync(Stg + j * 16, acc[i][j], 64,
                                    wmma::mem_row_major);
        __syncwarp();
        const int rbase = row0 + wm * 32 + i * 16;
#pragma unroll
        for (int rr = 0; rr < 16; rr++) {
            float2 v = *(float2*)&Stg[rr * 64 + lane * 2];
            if (OH) {
                *(__half2*)&Hout[(size_t)(rbase + rr) * D_MODEL + colL + cb + lane * 2]
                    = __floats2half2_rn(v.x + bx, v.y + by);
            } else {
                float2 o; o.x = v.x + bx; o.y = v.y + by;
                *(float2*)&Cf[(size_t)(rbase + rr) * D_MODEL + colL + cb + lane * 2] = o;
            }
        }
        __syncwarp();
    }
}

// ---------------------------------------------------------------------------
// fp16 wmma causal flash attention (unchanged from round 7, proven)
// ---------------------------------------------------------------------------
#define AT_LD 72
#define ATT_SMEM (4 * 64 * AT_LD * 2 + 2 * 64 * AT_LD * 4)   /* 73728 */

__global__ __launch_bounds__(256) void attn_wmma(
    const __half* __restrict__ q, const __half* __restrict__ k,
    const __half* __restrict__ v, __half* __restrict__ o)
{
    extern __shared__ __align__(16) char sm[];
    __half* Qh = (__half*)sm;
    __half* Kh = Qh + 64 * AT_LD;
    __half* Vh = Kh + 64 * AT_LD;
    __half* Ph = Vh + 64 * AT_LD;
    float*  Sf = (float*)(Ph + 64 * AT_LD);
    float*  Os = Sf + 64 * AT_LD;

    const int tid = threadIdx.x;
    const int wid = tid >> 5;
    const int wm  = wid & 3;
    const int wn  = wid >> 2;
    const int qt  = blockIdx.x;
    const int bh  = blockIdx.y;
    const int b   = bh >> 4;
    const int h   = bh & 15;
    const int qbase = qt * 64;

    const int srow = tid >> 2;
    const int sseg = (tid & 3) * 16;

    const __half* qp = q + ((size_t)b * SEQ + qbase) * D_MODEL + h * HDIM;

#pragma unroll
    for (int i = 0; i < 2; i++) {
        const int chunk = tid + i * 256;
        const int r = chunk >> 3, c8 = (chunk & 7) * 8;
        *(uint4*)&Qh[r * AT_LD + c8] = *(const uint4*)(qp + (size_t)r * D_MODEL + c8);
    }
    for (int idx = tid; idx < 64 * AT_LD; idx += 256) Os[idx] = 0.f;

    float m_i = -1e30f, l_i = 0.f;
    __syncthreads();

    for (int kt = 0; kt <= qt; kt++) {
        const size_t krow = (size_t)b * SEQ + kt * 64;
        const __half* kp = k + krow * D_MODEL + h * HDIM;
        const __half* vp = v + krow * D_MODEL + h * HDIM;
#pragma unroll
        for (int i = 0; i < 2; i++) {
            const int chunk = tid + i * 256;
            const int r = chunk >> 3, c8 = (chunk & 7) * 8;
            *(uint4*)&Kh[r * AT_LD + c8] = *(const uint4*)(kp + (size_t)r * D_MODEL + c8);
            *(uint4*)&Vh[r * AT_LD + c8] = *(const uint4*)(vp + (size_t)r * D_MODEL + c8);
        }
        __syncthreads();

        {
            wmma::fragment<wmma::accumulator, 16, 16, 16, float> sacc[2];
#pragma unroll
            for (int j = 0; j < 2; j++) wmma::fill_fragment(sacc[j], 0.f);
#pragma unroll
            for (int kk = 0; kk < 64; kk += 16) {
                wmma::fragment<wmma::matrix_a, 16, 16, 16, __half, wmma::row_major> af;
                wmma::load_matrix_sync(af, Qh + (wm * 16) * AT_LD + kk, AT_LD);
#pragma unroll
                for (int j = 0; j < 2; j++) {
                    wmma::fragment<wmma::matrix_b, 16, 16, 16, __half, wmma::col_major> bf;
                    wmma::load_matrix_sync(bf, Kh + (wn * 32 + j * 16) * AT_LD + kk, AT_LD);
                    wmma::mma_sync(sacc[j], af, bf, sacc[j]);
                }
            }
#pragma unroll
            for (int j = 0; j < 2; j++)
                wmma::store_matrix_sync(Sf + (wm * 16) * AT_LD + wn * 32 + j * 16,
                                        sacc[j], AT_LD, wmma::mem_row_major);
        }
        __syncthreads();

        {
            float x[16];
#pragma unroll
            for (int j = 0; j < 16; j++)
                x[j] = Sf[srow * AT_LD + sseg + j] * 0.125f;
            if (kt == qt) {
#pragma unroll
                for (int j = 0; j < 16; j++)
                    if (sseg + j > srow) x[j] = -1e30f;
            }
            float mx = x[0];
#pragma unroll
            for (int j = 1; j < 16; j++) mx = fmaxf(mx, x[j]);
            mx = fmaxf(mx, __shfl_xor_sync(0xffffffffu, mx, 1));
            mx = fmaxf(mx, __shfl_xor_sync(0xffffffffu, mx, 2));
            const float mnew  = fmaxf(m_i, mx);
            const float scale = __expf(m_i - mnew);
            float rs = 0.f;
#pragma unroll
            for (int j = 0; j < 16; j++) {
                x[j] = __expf(x[j] - mnew);
                rs += x[j];
            }
            rs += __shfl_xor_sync(0xffffffffu, rs, 1);
            rs += __shfl_xor_sync(0xffffffffu, rs, 2);
            l_i = l_i * scale + rs;
            m_i = mnew;
#pragma unroll
            for (int j = 0; j < 16; j++)
                Os[srow * AT_LD + sseg + j] *= scale;
#pragma unroll
            for (int j = 0; j < 16; j += 2)
                *(__half2*)&Ph[srow * AT_LD + sseg + j] =
                    __floats2half2_rn(x[j], x[j + 1]);
        }
        __syncthreads();

        {
            wmma::fragment<wmma::accumulator, 16, 16, 16, float> oacc[2];
#pragma unroll
            for (int j = 0; j < 2; j++)
                wmma::load_matrix_sync(oacc[j],
                    Os + (wm * 16) * AT_LD + wn * 32 + j * 16, AT_LD,
                    wmma::mem_row_major);
#pragma unroll
            for (int kk = 0; kk < 64; kk += 16) {
                wmma::fragment<wmma::matrix_a, 16, 16, 16, __half, wmma::row_major> af;
                wmma::load_matrix_sync(af, Ph + (wm * 16) * AT_LD + kk, AT_LD);
#pragma unroll
                for (int j = 0; j < 2; j++) {
                    wmma::fragment<wmma::matrix_b, 16, 16, 16, __half, wmma::row_major> bf;
                    wmma::load_matrix_sync(bf, Vh + kk * AT_LD + wn * 32 + j * 16, AT_LD);
                    wmma::mma_sync(oacc[j], af, bf, oacc[j]);
                }
            }
#pragma unroll
            for (int j = 0; j < 2; j++)
                wmma::store_matrix_sync(Os + (wm * 16) * AT_LD + wn * 32 + j * 16,
                                        oacc[j], AT_LD, wmma::mem_row_major);
        }
        __syncthreads();
    }

    {
        const float inv = 1.f / l_i;
        __half* op = o + ((size_t)b * SEQ + qbase + srow) * D_MODEL + h * HDIM;
#pragma unroll
        for (int j = 0; j < 16; j += 2)
            *(__half2*)&op[sseg + j] = __floats2half2_rn(
                Os[srow * AT_LD + sseg + j] * inv,
                Os[srow * AT_LD + sseg + j + 1] * inv);
    }
}

// ---------------------------------------------------------------------------
extern "C" void kernel_launch(void* const* d_in, const int* in_sizes, int n_in,
                              void* d_out, int out_size)
{
    (void)in_sizes; (void)n_in; (void)out_size;
    const float* x  = (const float*)d_in[0];
    const float* Wq = (const float*)d_in[1];
    const float* bq = (const float*)d_in[2];
    const float* Wk = (const float*)d_in[3];
    const float* bk = (const float*)d_in[4];
    const float* Wv = (const float*)d_in[5];
    const float* bv = (const float*)d_in[6];
    const float* Wo = (const float*)d_in[7];
    const float* bo = (const float*)d_in[8];
    float* out = (float*)d_out;

    __half *gqh, *gkh, *gvh, *gxh, *goh, *gwth;
    cudaGetSymbolAddress((void**)&gqh, g_qh);
    cudaGetSymbolAddress((void**)&gkh, g_kh);
    cudaGetSymbolAddress((void**)&gvh, g_vh);
    cudaGetSymbolAddress((void**)&gxh, g_xh);
    cudaGetSymbolAddress((void**)&goh, g_oh);
    cudaGetSymbolAddress((void**)&gwth, g_wth);
    __half* wto = gwth + 3 * (size_t)D_MODEL * D_MODEL;

    const int NELEM = MROWS * D_MODEL;

    cudaFuncSetAttribute(attn_wmma,
                         cudaFuncAttributeMaxDynamicSharedMemorySize, ATT_SMEM);

    dim3 gt(32, 32, 4);
    transpose_f2h4<<<gt, 256>>>(Wq, Wk, Wv, Wo, gwth);
    f2h<<<NELEM / (256 * 8), 256>>>(x, gxh, NELEM);

    // Fused QKV projection: N = 3072, half outputs
    dim3 gqkv(3 * D_MODEL / BN, MROWS / BM);   // (24, 64)
    gemm_h<true><<<gqkv, 256>>>(gxh, gwth, bq, bk, bv,
                                nullptr, gqh, gkh, gvh);

    dim3 ga(SEQ / 64, BATCH * HEADS);          // (32, 64)
    attn_wmma<<<ga, 256, ATT_SMEM>>>(gqh, gkh, gvh, goh);

    // Output projection: fp32 out
    dim3 go(D_MODEL / BN, MROWS / BM);         // (8, 64)
    gemm_h<false><<<go, 256>>>(goh, wto, bo, nullptr, nullptr,
                               out, nullptr, nullptr, nullptr);
}

// round 10
// speedup vs baseline: 8.2712x; 1.4454x over previous
#include <cuda_runtime.h>
#include <cuda_fp16.h>
#include <mma.h>
#include <cstddef>
#include <cstdint>

using namespace nvcuda;

#define D_MODEL 1024
#define SEQ     2048
#define BATCH   4
#define HEADS   16
#define HDIM    64
#define MROWS   (BATCH * SEQ)   /* 8192 */

// Scratch (alloc-free rule: __device__ globals)
__device__ __half g_qh[MROWS * D_MODEL];
__device__ __half g_kh[MROWS * D_MODEL];
__device__ __half g_vh[MROWS * D_MODEL];
__device__ __half g_xh[MROWS * D_MODEL];
__device__ __half g_oh[MROWS * D_MODEL];
__device__ __half g_wth[4 * D_MODEL * D_MODEL];   // transposed half weights (q,k,v,o)

// ---------------------------------------------------------------------------
// helpers
// ---------------------------------------------------------------------------
__device__ __forceinline__ uint32_t smem_u32(const void* p) {
    uint32_t a;
    asm("{ .reg .u64 t; cvta.to.shared.u64 t, %1; cvt.u32.u64 %0, t; }"
        : "=r"(a) : "l"(p));
    return a;
}
__device__ __forceinline__ void cp_async16(uint32_t dst, const void* src) {
    asm volatile("cp.async.cg.shared.global [%0], [%1], 16;"
                 :: "r"(dst), "l"(__cvta_generic_to_global(src)) : "memory");
}
__device__ __forceinline__ void cp_commit() {
    asm volatile("cp.async.commit_group;" ::: "memory");
}
template <int N>
__device__ __forceinline__ void cp_wait() {
    asm volatile("cp.async.wait_group %0;" :: "n"(N) : "memory");
}
__device__ __forceinline__ void ldsm4(uint32_t r[4], uint32_t addr) {
    asm volatile("ldmatrix.sync.aligned.m8n8.x4.shared.b16 {%0,%1,%2,%3}, [%4];"
                 : "=r"(r[0]), "=r"(r[1]), "=r"(r[2]), "=r"(r[3]) : "r"(addr));
}
__device__ __forceinline__ void ldsm4t(uint32_t r[4], uint32_t addr) {
    asm volatile("ldmatrix.sync.aligned.m8n8.x4.trans.shared.b16 {%0,%1,%2,%3}, [%4];"
                 : "=r"(r[0]), "=r"(r[1]), "=r"(r[2]), "=r"(r[3]) : "r"(addr));
}
__device__ __forceinline__ void mma16816(float d[4], const uint32_t a[4],
                                         uint32_t b0, uint32_t b1) {
    asm volatile(
        "mma.sync.aligned.m16n8k16.row.col.f32.f16.f16.f32 "
        "{%0,%1,%2,%3}, {%4,%5,%6,%7}, {%8,%9}, {%0,%1,%2,%3};"
        : "+f"(d[0]), "+f"(d[1]), "+f"(d[2]), "+f"(d[3])
        : "r"(a[0]), "r"(a[1]), "r"(a[2]), "r"(a[3]), "r"(b0), "r"(b1));
}
__device__ __forceinline__ uint32_t h2pack(float x, float y) {
    __half2 h = __floats2half2_rn(x, y);
    return *(uint32_t*)&h;
}

// ---------------------------------------------------------------------------
// Converters
// ---------------------------------------------------------------------------
__global__ __launch_bounds__(256) void f2h(const float* __restrict__ in,
                                           __half* __restrict__ out, int n)
{
    const int i = (blockIdx.x * 256 + threadIdx.x) * 8;
    if (i < n) {
        float4 a = *(const float4*)(in + i);
        float4 b = *(const float4*)(in + i + 4);
        __half2 h[4];
        h[0] = __floats2half2_rn(a.x, a.y);
        h[1] = __floats2half2_rn(a.z, a.w);
        h[2] = __floats2half2_rn(b.x, b.y);
        h[3] = __floats2half2_rn(b.z, b.w);
        *(uint4*)(out + i) = *(uint4*)h;
    }
}

__global__ __launch_bounds__(256) void transpose_f2h4(
    const float* __restrict__ W0, const float* __restrict__ W1,
    const float* __restrict__ W2, const float* __restrict__ W3,
    __half* __restrict__ outbase)
{
    __shared__ float t[32][33];
    const int z = blockIdx.z;
    const float* in = (z == 0) ? W0 : (z == 1) ? W1 : (z == 2) ? W2 : W3;
    __half* out = outbase + (size_t)z * D_MODEL * D_MODEL;
    const int bx = blockIdx.x * 32, by = blockIdx.y * 32;
    const int x = threadIdx.x & 31, y0 = threadIdx.x >> 5;
#pragma unroll
    for (int i = 0; i < 32; i += 8)
        t[y0 + i][x] = in[(size_t)(by + y0 + i) * D_MODEL + bx + x];
    __syncthreads();
#pragma unroll
    for (int i = 0; i < 32; i += 8)
        out[(size_t)(bx + y0 + i) * D_MODEL + by + x] = __float2half(t[x][y0 + i]);
}

// ---------------------------------------------------------------------------
// fp16 tensor-core GEMM (unchanged from round 9, proven)
// ---------------------------------------------------------------------------
#define BM 128
#define BN 128
#define BKH 32
#define LDH 40
#define TILE_H (128 * LDH)
#define STAGE_B (2 * TILE_H * 2)
#define GK 1024

template <bool OH>
__global__ __launch_bounds__(256) void gemm_h(
    const __half* __restrict__ A, const __half* __restrict__ BT,
    const float* __restrict__ bias0, const float* __restrict__ bias1,
    const float* __restrict__ bias2,
    float* __restrict__ Cf,
    __half* __restrict__ H0, __half* __restrict__ H1, __half* __restrict__ H2)
{
    __shared__ __align__(16) char sm[2 * STAGE_B];
    const uint32_t sb = smem_u32(sm);

    const int tid   = threadIdx.x;
    const int wid   = tid >> 5;
    const int lane  = tid & 31;
    const int wm    = wid >> 1;
    const int wn    = wid & 1;
    const int row0  = blockIdx.y * BM;
    const int col0g = blockIdx.x * BN;
    const int seg   = col0g >> 10;
    const int colL  = col0g & 1023;
    const float* bias = (seg == 0) ? bias0 : (seg == 1) ? bias1 : bias2;
    __half* Hout      = (seg == 0) ? H0    : (seg == 1) ? H1    : H2;

    wmma::fragment<wmma::accumulator, 16, 16, 16, float> acc[2][4];
#pragma unroll
    for (int i = 0; i < 2; i++)
#pragma unroll
        for (int j = 0; j < 4; j++) wmma::fill_fragment(acc[i][j], 0.f);

    const int r0 = tid >> 2;
    const int c0 = (tid & 3) * 8;

    auto load_stage = [&](int k0, int s) {
        const uint32_t abase = sb + s * STAGE_B;
        const uint32_t bbase = abase + TILE_H * 2;
#pragma unroll
        for (int i = 0; i < 2; i++) {
            const int r = r0 + i * 64;
            cp_async16(abase + (r * LDH + c0) * 2,
                       A + (size_t)(row0 + r) * GK + k0 + c0);
        }
#pragma unroll
        for (int i = 0; i < 2; i++) {
            const int r = r0 + i * 64;
            cp_async16(bbase + (r * LDH + c0) * 2,
                       BT + (size_t)(col0g + r) * GK + k0 + c0);
        }
        cp_commit();
    };

    load_stage(0, 0);

    const int NIT = GK / BKH;
    for (int it = 0; it < NIT; it++) {
        const int s = it & 1;
        if (it + 1 < NIT) { load_stage((it + 1) * BKH, s ^ 1); cp_wait<1>(); }
        else              { cp_wait<0>(); }
        __syncthreads();

        const __half* smA = (const __half*)(sm + s * STAGE_B);
        const __half* smB = smA + TILE_H;

#pragma unroll
        for (int kk = 0; kk < BKH; kk += 16) {
            wmma::fragment<wmma::matrix_a, 16, 16, 16, __half, wmma::row_major> af[2];
            wmma::fragment<wmma::matrix_b, 16, 16, 16, __half, wmma::col_major> bf[4];
#pragma unroll
            for (int i = 0; i < 2; i++)
                wmma::load_matrix_sync(af[i], smA + (wm * 32 + i * 16) * LDH + kk, LDH);
#pragma unroll
            for (int j = 0; j < 4; j++)
                wmma::load_matrix_sync(bf[j], smB + (wn * 64 + j * 16) * LDH + kk, LDH);
#pragma unroll
            for (int i = 0; i < 2; i++)
#pragma unroll
                for (int j = 0; j < 4; j++)
                    wmma::mma_sync(acc[i][j], af[i], bf[j], acc[i][j]);
        }
        __syncthreads();
    }

    float* Stg = (float*)sm + wid * 16 * 64;
    const int cb = wn * 64;
    const float bx = bias[colL + cb + lane * 2];
    const float by = bias[colL + cb + lane * 2 + 1];
#pragma unroll
    for (int i = 0; i < 2; i++) {
#pragma unroll
        for (int j = 0; j < 4; j++)
            wmma::store_matrix_sync(Stg + j * 16, acc[i][j], 64,
                                    wmma::mem_row_major);
        __syncwarp();
        const int rbase = row0 + wm * 32 + i * 16;
#pragma unroll
        for (int rr = 0; rr < 16; rr++) {
            float2 v = *(float2*)&Stg[rr * 64 + lane * 2];
            if (OH) {
                *(__half2*)&Hout[(size_t)(rbase + rr) * D_MODEL + colL + cb + lane * 2]
                    = __floats2half2_rn(v.x + bx, v.y + by);
            } else {
                float2 o; o.x = v.x + bx; o.y = v.y + by;
                *(float2*)&Cf[(size_t)(rbase + rr) * D_MODEL + colL + cb + lane * 2] = o;
            }
        }
        __syncwarp();
    }
}

// ---------------------------------------------------------------------------
// FA2-style causal attention with mma.sync + ldmatrix, register-resident
// softmax and O accumulator.
// CTA = 128 Q rows, 8 warps x 16 rows. KV tiles of 64, cp.async double-buffer.
// ---------------------------------------------------------------------------
#define ALD 72                       // halves per smem row (144B, ldmatrix CF)
#define KVT_B (64 * ALD * 2)         // 9216 B per tile
#define AQ_OFF (4 * KVT_B)           // Q staging after 2x(K,V)
#define ATT_SMEM (AQ_OFF + 128 * ALD * 2)   /* 36864 + 18432 = 55296 */

__global__ __launch_bounds__(256, 2) void attn_mma(
    const __half* __restrict__ q, const __half* __restrict__ k,
    const __half* __restrict__ v, __half* __restrict__ o)
{
    extern __shared__ __align__(16) char sm[];
    const uint32_t sb = smem_u32(sm);

    const int tid  = threadIdx.x;
    const int lane = tid & 31;
    const int w    = tid >> 5;
    const int qt   = (gridDim.x - 1) - blockIdx.x;   // big tiles first
    const int bh   = blockIdx.y;
    const int b    = bh >> 4;
    const int h    = bh & 15;
    const int qbase = qt * 128;

    const __half* qp = q + ((size_t)b * SEQ + qbase) * D_MODEL + h * HDIM;

    // Q: 128x64 -> 1024 16B chunks, 4 per thread
#pragma unroll
    for (int i = 0; i < 4; i++) {
        const int idx = tid + i * 256;
        const int r = idx >> 3, c8 = (idx & 7) * 8;
        cp_async16(sb + AQ_OFF + (r * ALD + c8) * 2, qp + (size_t)r * D_MODEL + c8);
    }
    cp_commit();

    auto load_kv = [&](int kt, int s) {
        const size_t krow = (size_t)b * SEQ + kt * 64;
        const __half* kp = k + krow * D_MODEL + h * HDIM;
        const __half* vp = v + krow * D_MODEL + h * HDIM;
        const uint32_t kb = sb + s * 2 * KVT_B;
        const uint32_t vb = kb + KVT_B;
#pragma unroll
        for (int i = 0; i < 2; i++) {
            const int idx = tid + i * 256;
            const int r = idx >> 3, c8 = (idx & 7) * 8;
            cp_async16(kb + (r * ALD + c8) * 2, kp + (size_t)r * D_MODEL + c8);
            cp_async16(vb + (r * ALD + c8) * 2, vp + (size_t)r * D_MODEL + c8);
        }
        cp_commit();
    };
    load_kv(0, 0);

    // ldmatrix lane address components (same for all x4 uses)
    const int lrow = ((lane >> 3) & 1) * 8 + (lane & 7);   // row within 16
    const int lcol = (lane >> 4) * 8;                      // col-8 group

    cp_wait<1>();    // Q group retired
    __syncthreads();

    uint32_t qa[4][4];
#pragma unroll
    for (int kk = 0; kk < 4; kk++)
        ldsm4(qa[kk], sb + AQ_OFF +
              ((w * 16 + lrow) * ALD + kk * 16 + lcol) * 2);

    float oacc[8][4];
#pragma unroll
    for (int j = 0; j < 8; j++)
#pragma unroll
        for (int e = 0; e < 4; e++) oacc[j][e] = 0.f;
    float m0 = -1e30f, m1 = -1e30f, l0 = 0.f, l1 = 0.f;

    const int wrow0 = qbase + w * 16;
    const int ntiles = 2 * qt + 2;

    for (int kt = 0; kt < ntiles; kt++) {
        const int s = kt & 1;
        cp_wait<0>();
        __syncthreads();
        if (kt + 1 < ntiles) load_kv(kt + 1, s ^ 1);

        if (kt * 64 <= wrow0 + 15) {            // not fully masked for this warp
            const uint32_t kbb = sb + s * 2 * KVT_B;
            const uint32_t vbb = kbb + KVT_B;

            // ---- S = Q @ K^T ----
            float sacc[8][4];
#pragma unroll
            for (int j = 0; j < 8; j++)
#pragma unroll
                for (int e = 0; e < 4; e++) sacc[j][e] = 0.f;
#pragma unroll
            for (int kk = 0; kk < 4; kk++)
#pragma unroll
                for (int jj = 0; jj < 4; jj++) {
                    uint32_t kb4[4];
                    ldsm4(kb4, kbb + ((jj * 16 + lrow) * ALD + kk * 16 + lcol) * 2);
                    mma16816(sacc[2 * jj],     qa[kk], kb4[0], kb4[2]);
                    mma16816(sacc[2 * jj + 1], qa[kk], kb4[1], kb4[3]);
                }

            // ---- softmax in registers ----
#pragma unroll
            for (int j = 0; j < 8; j++)
#pragma unroll
                for (int e = 0; e < 4; e++) sacc[j][e] *= 0.125f;

            if (kt * 64 + 63 > wrow0) {         // partial tile: apply mask
                const int colb = kt * 64 + (lane & 3) * 2;
                const int r0g  = wrow0 + (lane >> 2);
#pragma unroll
                for (int j = 0; j < 8; j++) {
                    const int c = colb + j * 8;
                    if (c     > r0g)     sacc[j][0] = -1e30f;
                    if (c + 1 > r0g)     sacc[j][1] = -1e30f;
                    if (c     > r0g + 8) sacc[j][2] = -1e30f;
                    if (c + 1 > r0g + 8) sacc[j][3] = -1e30f;
                }
            }

            float mx0 = sacc[0][0], mx1 = sacc[0][2];
#pragma unroll
            for (int j = 0; j < 8; j++) {
                mx0 = fmaxf(mx0, fmaxf(sacc[j][0], sacc[j][1]));
                mx1 = fmaxf(mx1, fmaxf(sacc[j][2], sacc[j][3]));
            }
            mx0 = fmaxf(mx0, __shfl_xor_sync(0xffffffffu, mx0, 1));
            mx0 = fmaxf(mx0, __shfl_xor_sync(0xffffffffu, mx0, 2));
            mx1 = fmaxf(mx1, __shfl_xor_sync(0xffffffffu, mx1, 1));
            mx1 = fmaxf(mx1, __shfl_xor_sync(0xffffffffu, mx1, 2));

            const float mn0 = fmaxf(m0, mx0);
            const float mn1 = fmaxf(m1, mx1);
            const float a0 = __expf(m0 - mn0);
            const float a1 = __expf(m1 - mn1);
            m0 = mn0; m1 = mn1;

            float s0 = 0.f, s1 = 0.f;
#pragma unroll
            for (int j = 0; j < 8; j++) {
                sacc[j][0] = __expf(sacc[j][0] - mn0);
                sacc[j][1] = __expf(sacc[j][1] - mn0);
                sacc[j][2] = __expf(sacc[j][2] - mn1);
                sacc[j][3] = __expf(sacc[j][3] - mn1);
                s0 += sacc[j][0] + sacc[j][1];
                s1 += sacc[j][2] + sacc[j][3];
            }
            s0 += __shfl_xor_sync(0xffffffffu, s0, 1);
            s0 += __shfl_xor_sync(0xffffffffu, s0, 2);
            s1 += __shfl_xor_sync(0xffffffffu, s1, 1);
            s1 += __shfl_xor_sync(0xffffffffu, s1, 2);
            l0 = l0 * a0 + s0;
            l1 = l1 * a1 + s1;

#pragma unroll
            for (int j = 0; j < 8; j++) {
                oacc[j][0] *= a0; oacc[j][1] *= a0;
                oacc[j][2] *= a1; oacc[j][3] *= a1;
            }

            // ---- O += P @ V ----
#pragma unroll
            for (int t = 0; t < 4; t++) {
                uint32_t pa[4];
                pa[0] = h2pack(sacc[2 * t][0],     sacc[2 * t][1]);
                pa[1] = h2pack(sacc[2 * t][2],     sacc[2 * t][3]);
                pa[2] = h2pack(sacc[2 * t + 1][0], sacc[2 * t + 1][1]);
                pa[3] = h2pack(sacc[2 * t + 1][2], sacc[2 * t + 1][3]);
#pragma unroll
                for (int jj = 0; jj < 4; jj++) {
                    uint32_t vb4[4];
                    ldsm4t(vb4, vbb + ((t * 16 + lrow) * ALD + jj * 16 + lcol) * 2);
                    mma16816(oacc[2 * jj],     pa, vb4[0], vb4[1]);
                    mma16816(oacc[2 * jj + 1], pa, vb4[2], vb4[3]);
                }
            }
        }
    }

    // ---- epilogue ----
    const float i0 = 1.f / l0;
    const float i1 = 1.f / l1;
    const int r0g = qbase + w * 16 + (lane >> 2);
    __half* o0 = o + ((size_t)b * SEQ + r0g) * D_MODEL + h * HDIM + (lane & 3) * 2;
    __half* o1 = o0 + 8 * D_MODEL;
#pragma unroll
    for (int j = 0; j < 8; j++) {
        *(__half2*)(o0 + j * 8) = __floats2half2_rn(oacc[j][0] * i0, oacc[j][1] * i0);
        *(__half2*)(o1 + j * 8) = __floats2half2_rn(oacc[j][2] * i1, oacc[j][3] * i1);
    }
}

// ---------------------------------------------------------------------------
extern "C" void kernel_launch(void* const* d_in, const int* in_sizes, int n_in,
                              void* d_out, int out_size)
{
    (void)in_sizes; (void)n_in; (void)out_size;
    const float* x  = (const float*)d_in[0];
    const float* Wq = (const float*)d_in[1];
    const float* bq = (const float*)d_in[2];
    const float* Wk = (const float*)d_in[3];
    const float* bk = (const float*)d_in[4];
    const float* Wv = (const float*)d_in[5];
    const float* bv = (const float*)d_in[6];
    const float* Wo = (const float*)d_in[7];
    const float* bo = (const float*)d_in[8];
    float* out = (float*)d_out;

    __half *gqh, *gkh, *gvh, *gxh, *goh, *gwth;
    cudaGetSymbolAddress((void**)&gqh, g_qh);
    cudaGetSymbolAddress((void**)&gkh, g_kh);
    cudaGetSymbolAddress((void**)&gvh, g_vh);
    cudaGetSymbolAddress((void**)&gxh, g_xh);
    cudaGetSymbolAddress((void**)&goh, g_oh);
    cudaGetSymbolAddress((void**)&gwth, g_wth);
    __half* wto = gwth + 3 * (size_t)D_MODEL * D_MODEL;

    const int NELEM = MROWS * D_MODEL;

    cudaFuncSetAttribute(attn_mma,
                         cudaFuncAttributeMaxDynamicSharedMemorySize, ATT_SMEM);

    dim3 gt(32, 32, 4);
    transpose_f2h4<<<gt, 256>>>(Wq, Wk, Wv, Wo, gwth);
    f2h<<<NELEM / (256 * 8), 256>>>(x, gxh, NELEM);

    dim3 gqkv(3 * D_MODEL / BN, MROWS / BM);   // (24, 64)
    gemm_h<true><<<gqkv, 256>>>(gxh, gwth, bq, bk, bv,
                                nullptr, gqh, gkh, gvh);

    dim3 ga(SEQ / 128, BATCH * HEADS);         // (16, 64)
    attn_mma<<<ga, 256, ATT_SMEM>>>(gqh, gkh, gvh, goh);

    dim3 go(D_MODEL / BN, MROWS / BM);         // (8, 64)
    gemm_h<false><<<go, 256>>>(goh, wto, bo, nullptr, nullptr,
                               out, nullptr, nullptr, nullptr);
}